// round 7
// baseline (speedup 1.0000x reference)
#include <cuda_runtime.h>
#include <stdint.h>

#define BB 256
#define LL 8192
#define EE 64
#define M3 2731            // ceil(L/3) chain nodes (patch starts are multiples of 3)
#define ROWB 2752          // scratch row stride (bytes), 16B aligned, zero pad
#define NT2 512            // kernel B threads
#define CH 6               // m-nodes per chunk: 512*6 = 3072 >= 2731
#define PKS 3080           // smem byte array size in kernel B

__device__ uint8_t g_scratch[BB * ROWB];   // (sum3<<1)|bit per m-node, zero-padded

#define BYTEJ(j) ((int)((bw[(j) >> 2] >> (((j) & 3) * 8)) & 0xFF))

// ===================== Kernel A: entropy + per-group byte emit ==============
__global__ __launch_bounds__(256)
void entropy_kernel(const int* __restrict__ x, float* __restrict__ out_ent)
{
    const int g    = blockIdx.x * 256 + threadIdx.x;   // 0..262143
    const int r    = g >> 10;                          // row
    const int p0   = (g & 1023) << 3;                  // position in row
    const int lane = threadIdx.x & 31;
    const unsigned FULL = 0xffffffffu;

    // register tables via shfl broadcast (lane c holds entry c)
    float fl    = (float)lane;
    float clogv = (lane >= 2) ? fl * log2f(fl) : 0.0f;   // c*log2(c)
    float fl1   = fl + 1.0f;
    float dtabv = fl1 * log2f(fl1) - clogv;              // dlog(c)

    // load 5 words: tokens [p0-4, p0+16), clamped within the row
    const int4* xv4 = (const int4*)(x + (long)r * LL);
    unsigned bw[5];
    {
        int wbase = (p0 >> 2) - 1;
        #pragma unroll
        for (int q = 0; q < 5; q++) {
            int w = wbase + q;
            w = w < 0 ? 0 : (w > 2047 ? 2047 : w);
            int4 v = xv4[w];
            bw[q] = (unsigned)v.x | ((unsigned)v.y << 8) |
                    ((unsigned)v.z << 16) | ((unsigned)v.w << 24);
        }
    }

    // initial histogram: bytes 0..8 (tokens [p0-4, p0+4]); edges self-correct
    int hp = 0;
    #pragma unroll
    for (int jj = 0; jj <= 8; jj++) hp += 1 << (BYTEJ(jj) * 6);
    float S = 0.0f;
    #pragma unroll
    for (int q = 0; q < 5; q++) {
        int c = (hp >> (6 * q)) & 63;
        S += __shfl_sync(FULL, clogv, c);
    }

    int rr = p0 % 3;
    int m  = (p0 + 2) / 3;               // first m with 3m >= p0
    uint8_t* srow = g_scratch + (long)r * ROWB;
    float* erow = out_ent + (long)r * LL + p0;
    float4 ebuf;

    #pragma unroll
    for (int k = 0; k < 8; k++) {
        float ent = 3.16992500144f - S * (1.0f / 9.0f);    // uniform interior
        if      ((k & 3) == 0) ebuf.x = ent;
        else if ((k & 3) == 1) ebuf.y = ent;
        else if ((k & 3) == 2) ebuf.z = ent;
        else {
            ebuf.w = ent;
            *reinterpret_cast<float4*>(erow + (k - 3)) = ebuf;
        }

        if (rr == 0) {                   // token p0+k = 3m
            int s3 = BYTEJ(k + 4) + BYTEJ(k + 5);
            if (p0 + k + 2 < LL) s3 += BYTEJ(k + 6);     // third token if in range
            srow[m] = (uint8_t)((s3 << 1) | (ent > 1.5f ? 1 : 0));
            m++;
        }
        rr = (rr == 2) ? 0 : rr + 1;

        // slide i -> i+1: drop token i-4 (byte k), add token i+5 (byte k+9)
        if (k < 7) {
            int sh1 = BYTEJ(k) * 6;
            int c_out = (hp >> sh1) & 63;
            float dl_out = __shfl_sync(FULL, dtabv, c_out - 1);
            hp -= 1 << sh1;  S -= dl_out;
            int sh2 = BYTEJ(k + 9) * 6;
            int c_in = (hp >> sh2) & 63;
            float dl_in = __shfl_sync(FULL, dtabv, c_in);
            hp += 1 << sh2;  S += dl_in;
        }
    }

    // ---- row-start fixup: first 4 entropies have clipped windows ----
    if (p0 == 0) {
        int hp2 = 0;
        #pragma unroll
        for (int j = 4; j <= 7; j++) hp2 += 1 << (BYTEJ(j) * 6);   // tokens 0..3
        float ee[4];
        #pragma unroll
        for (int k = 0; k < 4; k++) {
            hp2 += 1 << (BYTEJ(k + 8) * 6);                        // token k+4
            float tot = (float)(k + 5);
            float S2 = 0.0f;
            #pragma unroll
            for (int q = 0; q < 5; q++) {
                float fc = (float)((hp2 >> (6 * q)) & 63);
                S2 += fc * log2f(fmaxf(fc, 1.0f));
            }
            ee[k] = log2f(tot) - S2 / tot;
        }
        float4 ev; ev.x = ee[0]; ev.y = ee[1]; ev.z = ee[2]; ev.w = ee[3];
        *reinterpret_cast<float4*>(erow) = ev;
        int s0 = BYTEJ(4) + BYTEJ(5) + BYTEJ(6);                   // tokens 0..2
        int s1 = BYTEJ(7) + BYTEJ(8) + BYTEJ(9);                   // tokens 3..5
        srow[0] = (uint8_t)((s0 << 1) | (ee[0] > 1.5f ? 1 : 0));   // m=0 (k=0)
        srow[1] = (uint8_t)((s1 << 1) | (ee[3] > 1.5f ? 1 : 0));   // m=1 (k=3)
    }

    // ---- row-end fixup: last 4 entropies (i = 8188..8191) ----
    if (p0 == LL - 8) {
        int hp2 = 0;
        #pragma unroll
        for (int j = 4; j <= 11; j++) hp2 += 1 << (BYTEJ(j) * 6);  // tokens 8184..8191
        float ee[4];
        #pragma unroll
        for (int d = 0; d < 4; d++) {
            float tot = (float)(8 - d);
            float S2 = 0.0f;
            #pragma unroll
            for (int q = 0; q < 5; q++) {
                float fc = (float)((hp2 >> (6 * q)) & 63);
                S2 += fc * log2f(fmaxf(fc, 1.0f));
            }
            ee[d] = log2f(tot) - S2 / tot;
            hp2 -= 1 << (BYTEJ(4 + d) * 6);                        // drop leftmost
        }
        float4 ev; ev.x = ee[0]; ev.y = ee[1]; ev.z = ee[2]; ev.w = ee[3];
        *reinterpret_cast<float4*>(erow + 4) = ev;                 // i=8188..8191
        int s3 = BYTEJ(10) + BYTEJ(11);                            // tokens 8190,8191
        srow[2730] = (uint8_t)((s3 << 1) | (ee[2] > 1.5f ? 1 : 0)); // m=2730 (i=8190)
    }
}

// ===================== Kernel B: chain walk + MLP ===========================
__device__ __forceinline__ unsigned compose4(unsigned e0, unsigned e1, unsigned e2,
                                             unsigned e3, unsigned p) {
    unsigned r1 = p & 3u;
    unsigned a   = (r1 & 1u) ? e1 : e0;
    unsigned bb_ = (r1 & 1u) ? e3 : e2;
    unsigned own = (r1 & 2u) ? bb_ : a;
    return own + (p & ~3u);
}

__global__ __launch_bounds__(NT2, 2)
void chain_kernel(const float* __restrict__ w1,
                  const float* __restrict__ b1,
                  const float* __restrict__ w2,
                  const float* __restrict__ b2,
                  float* __restrict__ out_feat)
{
    __shared__ uint8_t  pk_s[PKS];           // scratch bytes + zero pad
    __shared__ int      hist_s[16 * 64];
    __shared__ int      hist_tot_s[52];
    __shared__ unsigned wm_s[64];
    __shared__ unsigned wb0_s[17];
    __shared__ unsigned g0_s[NT2];
    __shared__ float    clip_mean_s;
    __shared__ int      clip_flag_s;
    __shared__ float    hpart_s[8 * EE];
    __shared__ float    havg_s[EE];

    const int b = blockIdx.x;
    const int t = threadIdx.x;
    const int lane = t & 31;
    const int wid  = t >> 5;
    const unsigned FULL = 0xffffffffu;

    // ---- stage scratch row into smem (coalesced u32 loads) ----
    {
        const uint32_t* src = (const uint32_t*)(g_scratch + (long)b * ROWB);
        uint32_t* dst = (uint32_t*)pk_s;
        if (t < 688) dst[t] = src[t];                    // 2752 bytes
        int w2i = t + NT2 - 512 + 512;                   // t+512
        if (w2i >= 688 && w2i < PKS / 4) dst[w2i] = 0u;  // zero pad 688..769
        else if (w2i < 688) dst[w2i] = src[w2i];
    }
    hist_s[t] = 0;
    hist_s[t + NT2] = 0;
    if (t == 0) { clip_flag_s = 0; clip_mean_s = 0.0f; }
    __syncthreads();

    // ---- phase A: 4 candidate chains per chunk (bit = LSB of byte) ----
    unsigned e0, e1, e2, e3;
    {
        const int mend = CH * (t + 1);
        int mm0 = CH * t + 0, mm1 = CH * t + 1, mm2 = CH * t + 2, mm3 = CH * t + 3;
        int cc0 = 0, cc1 = 0, cc2 = 0, cc3 = 0;
        #pragma unroll
        for (int it = 0; it < CH; it++) {
            int pk0 = pk_s[mm0], pk1 = pk_s[mm1];
            int pk2 = pk_s[mm2], pk3 = pk_s[mm3];
            bool a0 = mm0 < mend, a1 = mm1 < mend, a2 = mm2 < mend, a3 = mm3 < mend;
            cc0 += (a0 && mm0 < M3) ? 1 : 0;
            cc1 += (a1 && mm1 < M3) ? 1 : 0;
            cc2 += (a2 && mm2 < M3) ? 1 : 0;
            cc3 += (a3 && mm3 < M3) ? 1 : 0;
            mm0 += a0 ? ((pk0 & 1) ? 1 : 4) : 0;
            mm1 += a1 ? ((pk1 & 1) ? 1 : 4) : 0;
            mm2 += a2 ? ((pk2 & 1) ? 1 : 4) : 0;
            mm3 += a3 ? ((pk3 & 1) ? 1 : 4) : 0;
        }
        e0 = ((unsigned)cc0 << 2) | (unsigned)(mm0 - mend);
        e1 = ((unsigned)cc1 << 2) | (unsigned)(mm1 - mend);
        e2 = ((unsigned)cc2 << 2) | (unsigned)(mm2 - mend);
        e3 = ((unsigned)cc3 << 2) | (unsigned)(mm3 - mend);
    }

    // ---- intra-warp inclusive composition scan ----
    #pragma unroll
    for (int d = 1; d < 32; d <<= 1) {
        unsigned p0 = __shfl_up_sync(FULL, e0, d);
        unsigned p1 = __shfl_up_sync(FULL, e1, d);
        unsigned p2 = __shfl_up_sync(FULL, e2, d);
        unsigned p3 = __shfl_up_sync(FULL, e3, d);
        if (lane >= d) {
            unsigned n0 = compose4(e0, e1, e2, e3, p0);
            unsigned n1 = compose4(e0, e1, e2, e3, p1);
            unsigned n2 = compose4(e0, e1, e2, e3, p2);
            unsigned n3 = compose4(e0, e1, e2, e3, p3);
            e0 = n0; e1 = n1; e2 = n2; e3 = n3;
        }
    }
    if (lane == 31) {
        wm_s[wid * 4 + 0] = e0; wm_s[wid * 4 + 1] = e1;
        wm_s[wid * 4 + 2] = e2; wm_s[wid * 4 + 3] = e3;
    }
    __syncthreads();

    // ---- inter-warp composition scan of the 16 warp maps (warp 0) ----
    if (wid == 0) {
        unsigned f0 = (lane < 16) ? wm_s[lane * 4 + 0] : 0u;
        unsigned f1 = (lane < 16) ? wm_s[lane * 4 + 1] : 1u;
        unsigned f2 = (lane < 16) ? wm_s[lane * 4 + 2] : 2u;
        unsigned f3 = (lane < 16) ? wm_s[lane * 4 + 3] : 3u;
        #pragma unroll
        for (int d = 1; d < 16; d <<= 1) {
            unsigned p0 = __shfl_up_sync(FULL, f0, d);
            unsigned p1 = __shfl_up_sync(FULL, f1, d);
            unsigned p2 = __shfl_up_sync(FULL, f2, d);
            unsigned p3 = __shfl_up_sync(FULL, f3, d);
            if (lane >= d && lane < 16) {
                unsigned n0 = compose4(f0, f1, f2, f3, p0);
                unsigned n1 = compose4(f0, f1, f2, f3, p1);
                unsigned n2 = compose4(f0, f1, f2, f3, p2);
                unsigned n3 = compose4(f0, f1, f2, f3, p3);
                f0 = n0; f1 = n1; f2 = n2; f3 = n3;
            }
        }
        if (lane < 16)  wb0_s[lane + 1] = f0;
        if (lane == 31) wb0_s[0] = 0u;
    }
    __syncthreads();

    g0_s[t] = compose4(e0, e1, e2, e3, wb0_s[wid]);
    __syncthreads();

    // ---- phase B: walk real path, histogram patch sums ----
    {
        unsigned ge = (t == 0) ? 0u : g0_s[t - 1];
        int m = CH * t + (int)(ge & 3u);
        const int mend = CH * (t + 1);
        int* hw = &hist_s[wid * 64];
        while (m < mend) {
            int pk  = pk_s[m];
            int bit = pk & 1;
            int s   = bit ? 1 : 4;
            if (m < M3) {
                if (m + s <= 2730) {
                    int q;
                    if (bit) q = (pk >> 1) << 2;          // mean = sum3/3 = q/12
                    else q = (pk >> 1) + (pk_s[m+1] >> 1) + (pk_s[m+2] >> 1)
                           + (pk_s[m+3] >> 1);            // mean = q/12
                    atomicAdd(&hw[q], 1);
                } else {
                    // clipped final patch: j = L; padded bytes are zero
                    int fs = (pk >> 1);
                    if (!bit) fs += (pk_s[m+1] >> 1) + (pk_s[m+2] >> 1)
                                  + (pk_s[m+3] >> 1);
                    clip_mean_s = (float)fs / (float)(LL - 3 * m);
                    clip_flag_s = 1;
                }
            }
            m += s;
        }
    }
    __syncthreads();

    if (t < 49) {
        int s = 0;
        #pragma unroll
        for (int w = 0; w < 16; w++) s += hist_s[w * 64 + t];
        hist_tot_s[t] = s;
    }
    __syncthreads();

    // ---- MLP: hist-weighted relu accumulate ----
    {
        int e = t & 63;
        int g = t >> 6;                  // 0..7
        float w1e = w1[e];
        float b1e = b1[e];
        float acc = 0.0f;
        int q0 = g * 7;
        int q1 = q0 + 7; if (q1 > 49) q1 = 49;
        for (int q = q0; q < q1; q++) {
            int c = hist_tot_s[q];
            if (c) acc += (float)c * fmaxf(fmaf((float)q * (1.0f / 12.0f), w1e, b1e), 0.0f);
        }
        if (g == 0 && clip_flag_s)
            acc += fmaxf(fmaf(clip_mean_s, w1e, b1e), 0.0f);
        hpart_s[g * EE + e] = acc;
    }
    __syncthreads();

    if (t < EE) {
        float npf = (float)(g0_s[NT2 - 1] >> 2);
        float s = 0.0f;
        #pragma unroll
        for (int g = 0; g < 8; g++) s += hpart_s[g * EE + t];
        havg_s[t] = s / npf;
    }
    __syncthreads();

    if (t < EE) {
        const float4* w2r = reinterpret_cast<const float4*>(w2 + t * EE);
        float f = b2[t];
        #pragma unroll
        for (int kk = 0; kk < 16; kk++) {
            float4 wv = w2r[kk];
            f = fmaf(havg_s[4 * kk + 0], wv.x, f);
            f = fmaf(havg_s[4 * kk + 1], wv.y, f);
            f = fmaf(havg_s[4 * kk + 2], wv.z, f);
            f = fmaf(havg_s[4 * kk + 3], wv.w, f);
        }
        out_feat[(long)b * EE + t] = f;
    }
}

extern "C" void kernel_launch(void* const* d_in, const int* in_sizes, int n_in,
                              void* d_out, int out_size) {
    const int*   x  = (const int*)d_in[0];
    const float* w1 = (const float*)d_in[1];
    const float* b1 = (const float*)d_in[2];
    const float* w2 = (const float*)d_in[3];
    const float* b2 = (const float*)d_in[4];
    float* out = (float*)d_out;
    entropy_kernel<<<1024, 256>>>(x, out + BB * EE);
    chain_kernel<<<BB, NT2>>>(w1, b1, w2, b2, out);
}

// round 8
// speedup vs baseline: 1.1431x; 1.1431x over previous
#include <cuda_runtime.h>
#include <stdint.h>

#define BB 256
#define LL 8192
#define EE 64
#define M3 2731            // ceil(L/3) chain nodes (patch starts are multiples of 3)
#define NT 512             // threads per block (one row per block)
#define CH 6               // m-nodes per chunk: 512*6 = 3072 >= 2731
#define PKS 3080           // smem byte array (reads up to 3075), zero-padded tail

#define BYTEJ(j) ((int)((bw[(j) >> 2] >> (((j) & 3) * 8)) & 0xFF))

__device__ __forceinline__ unsigned compose4(unsigned e0, unsigned e1, unsigned e2,
                                             unsigned e3, unsigned p) {
    // apply p (earlier map) first, then own map {e0..e3}; value = (count<<2)|exit_off
    unsigned r1 = p & 3u;
    unsigned a   = (r1 & 1u) ? e1 : e0;
    unsigned bb_ = (r1 & 1u) ? e3 : e2;
    unsigned own = (r1 & 2u) ? bb_ : a;
    return own + (p & ~3u);
}

__global__ __launch_bounds__(NT, 2)
void patcher_kernel(const int* __restrict__ x,
                    const float* __restrict__ w1,
                    const float* __restrict__ b1,
                    const float* __restrict__ w2,
                    const float* __restrict__ b2,
                    float* __restrict__ out_feat,   // [B,E]
                    float* __restrict__ out_ent)    // [B,L]
{
    __shared__ uint32_t stage_s[2304];       // 2048 words + bank padding (w + w>>3)
    __shared__ float    clog_rep[512];       // clog[c*32+lane], conflict-free
    __shared__ float    dlog_rep[512];       // dlog[c*32+lane], conflict-free
    __shared__ uint8_t  pk_s[PKS];           // (sum3<<1)|bit per m-node, zero pad
    __shared__ int      hist_s[16 * 64];     // per-warp histograms over q in [0,48]
    __shared__ int      hist_tot_s[52];
    __shared__ unsigned wm_s[64];            // 16 warp maps x 4 entries
    __shared__ unsigned wb0_s[17];           // exclusive warp-base maps at entry 0
    __shared__ unsigned g0_s[NT];            // inclusive composite evaluated at 0
    __shared__ float    clip_mean_s;
    __shared__ int      clip_flag_s;
    __shared__ float    hpart_s[8 * EE];
    __shared__ float    havg_s[EE];

    const int b = blockIdx.x;
    const int t = threadIdx.x;
    const int lane = t & 31;
    const int wid  = t >> 5;                 // 0..15
    const unsigned FULL = 0xffffffffu;
    const int* __restrict__ xrow = x + (long)b * LL;

    // ---- init: tables, hist, zero pad ----
    {
        int c = t >> 5;
        float fc = (float)c;
        float cl = (c >= 2) ? fc * log2f(fc) : 0.0f;
        clog_rep[t] = cl;
        float f1 = fc + 1.0f;
        dlog_rep[t] = f1 * log2f(f1) - cl;
    }
    hist_s[t] = 0;
    hist_s[t + NT] = 0;
    if (t < 88) ((uint32_t*)pk_s)[682 + t] = 0u;   // zero bytes 2728..3079
    if (t == 0) { clip_flag_s = 0; clip_mean_s = 0.0f; }

    // ---- coalesced gmem load -> bank-padded byte staging ----
    {
        const int4* xv4 = (const int4*)xrow;
        #pragma unroll
        for (int j = 0; j < 4; j++) {
            int w = t + NT * j;
            int4 v = xv4[w];
            uint32_t pk = (unsigned)v.x | ((unsigned)v.y << 8) |
                          ((unsigned)v.z << 16) | ((unsigned)v.w << 24);
            stage_s[w + (w >> 3)] = pk;
        }
    }
    __syncthreads();

    // ---- window words: bw[q] = word 4t-1+q (clamped dup at edges) ----
    unsigned bw[6];
    {
        int w0 = 4 * t - 1; if (w0 < 0) w0 = 0;              // only t==0 clamps
        bw[0] = stage_s[w0 + (w0 >> 3)];
        #pragma unroll
        for (int q = 1; q < 5; q++) {
            int w = 4 * t - 1 + q;                           // always in range
            bw[q] = stage_s[w + (w >> 3)];
        }
        int w5 = 4 * t + 4; if (w5 > 2047) w5 = 2047;        // only t==NT-1 clamps
        bw[5] = stage_s[w5 + (w5 >> 3)];
    }

    // initial histogram: bytes 0..8 (uniform; edge threads self-correct)
    int hp = 0;
    #pragma unroll
    for (int jj = 0; jj <= 8; jj++) hp += 1 << (BYTEJ(jj) * 6);
    float S = 0.0f;
    #pragma unroll
    for (int q = 0; q < 5; q++) {
        int c = (hp >> (6 * q)) & 63;
        S += clog_rep[(c << 5) + lane];
    }

    int rr   = t % 3;                    // i0 % 3 (16 == 1 mod 3)
    int mreg = (16 * t + 2) / 3;         // first m with 3m >= 16t
    float* erow = out_ent + (long)b * LL + 16 * t;
    float4 ebuf;

    #pragma unroll
    for (int k = 0; k < 16; k++) {
        float ent = 3.16992500144f - S * (1.0f / 9.0f);    // uniform interior
        if      ((k & 3) == 0) ebuf.x = ent;
        else if ((k & 3) == 1) ebuf.y = ent;
        else if ((k & 3) == 2) ebuf.z = ent;
        else {
            ebuf.w = ent;
            *reinterpret_cast<float4*>(erow + (k - 3)) = ebuf;
        }

        if (rr == 0) {                   // token 16t+k = 3*mreg
            int s3 = BYTEJ(k + 4) + BYTEJ(k + 5) + BYTEJ(k + 6);
            pk_s[mreg] = (uint8_t)((s3 << 1) | (ent > 1.5f ? 1 : 0));
            mreg++;
        }
        rr = (rr == 2) ? 0 : rr + 1;

        // slide i -> i+1: drop token i-4 (byte k), add token i+5 (byte k+9)
        if (k < 15) {
            int sh1 = BYTEJ(k) * 6;                       // count >= 1 always
            int c_out = (hp >> sh1) & 63;
            S -= dlog_rep[((c_out - 1) << 5) + lane];
            hp -= 1 << sh1;
            int sh2 = BYTEJ(k + 9) * 6;
            int c_in = (hp >> sh2) & 63;
            S += dlog_rep[(c_in << 5) + lane];
            hp += 1 << sh2;
        }
    }

    // ---- edge fixups: recompute 4 clipped-window entropies + bytes ----
    if (t == 0) {
        int hp2 = 0;
        #pragma unroll
        for (int j = 4; j <= 7; j++) hp2 += 1 << (BYTEJ(j) * 6);   // tokens 0..3
        float ee[4];
        #pragma unroll
        for (int k = 0; k < 4; k++) {
            hp2 += 1 << (BYTEJ(k + 8) * 6);                        // token k+4
            float tot = (float)(k + 5);
            float S2 = 0.0f;
            #pragma unroll
            for (int q = 0; q < 5; q++) {
                float fc = (float)((hp2 >> (6 * q)) & 63);
                S2 += fc * log2f(fmaxf(fc, 1.0f));
            }
            ee[k] = log2f(tot) - S2 / tot;
        }
        float4 ev; ev.x = ee[0]; ev.y = ee[1]; ev.z = ee[2]; ev.w = ee[3];
        *reinterpret_cast<float4*>(erow) = ev;
        int s0 = BYTEJ(4) + BYTEJ(5) + BYTEJ(6);                   // tokens 0..2
        int s1 = BYTEJ(7) + BYTEJ(8) + BYTEJ(9);                   // tokens 3..5
        pk_s[0] = (uint8_t)((s0 << 1) | (ee[0] > 1.5f ? 1 : 0));   // m=0 (k=0)
        pk_s[1] = (uint8_t)((s1 << 1) | (ee[3] > 1.5f ? 1 : 0));   // m=1 (k=3)
    }
    if (t == NT - 1) {
        // bytes map token 16t-4+j: tokens 8184..8191 = bytes 12..19
        int hp2 = 0;
        #pragma unroll
        for (int j = 12; j <= 19; j++) hp2 += 1 << (BYTEJ(j) * 6);
        float ee[4];
        #pragma unroll
        for (int d = 0; d < 4; d++) {                              // i = 8188..8191
            float tot = (float)(8 - d);
            float S2 = 0.0f;
            #pragma unroll
            for (int q = 0; q < 5; q++) {
                float fc = (float)((hp2 >> (6 * q)) & 63);
                S2 += fc * log2f(fmaxf(fc, 1.0f));
            }
            ee[d] = log2f(tot) - S2 / tot;
            hp2 -= 1 << (BYTEJ(12 + d) * 6);                       // drop leftmost
        }
        float4 ev; ev.x = ee[0]; ev.y = ee[1]; ev.z = ee[2]; ev.w = ee[3];
        *reinterpret_cast<float4*>(erow + 12) = ev;
        int s3 = BYTEJ(18) + BYTEJ(19);                            // tokens 8190,8191
        pk_s[2730] = (uint8_t)((s3 << 1) | (ee[2] > 1.5f ? 1 : 0)); // m=2730 (i=8190)
    }
    __syncthreads();

    // ================= phase A: 4 candidate chains per chunk =================
    unsigned e0, e1, e2, e3;
    {
        const int mend = CH * (t + 1);
        int mm0 = CH * t + 0, mm1 = CH * t + 1, mm2 = CH * t + 2, mm3 = CH * t + 3;
        int cc0 = 0, cc1 = 0, cc2 = 0, cc3 = 0;
        #pragma unroll
        for (int it = 0; it < CH; it++) {
            int pk0 = pk_s[mm0], pk1 = pk_s[mm1];
            int pk2 = pk_s[mm2], pk3 = pk_s[mm3];
            bool a0 = mm0 < mend, a1 = mm1 < mend, a2 = mm2 < mend, a3 = mm3 < mend;
            cc0 += (a0 && mm0 < M3) ? 1 : 0;
            cc1 += (a1 && mm1 < M3) ? 1 : 0;
            cc2 += (a2 && mm2 < M3) ? 1 : 0;
            cc3 += (a3 && mm3 < M3) ? 1 : 0;
            mm0 += a0 ? ((pk0 & 1) ? 1 : 4) : 0;
            mm1 += a1 ? ((pk1 & 1) ? 1 : 4) : 0;
            mm2 += a2 ? ((pk2 & 1) ? 1 : 4) : 0;
            mm3 += a3 ? ((pk3 & 1) ? 1 : 4) : 0;
        }
        e0 = ((unsigned)cc0 << 2) | (unsigned)(mm0 - mend);
        e1 = ((unsigned)cc1 << 2) | (unsigned)(mm1 - mend);
        e2 = ((unsigned)cc2 << 2) | (unsigned)(mm2 - mend);
        e3 = ((unsigned)cc3 << 2) | (unsigned)(mm3 - mend);
    }

    // ---- intra-warp inclusive composition scan ----
    #pragma unroll
    for (int d = 1; d < 32; d <<= 1) {
        unsigned p0 = __shfl_up_sync(FULL, e0, d);
        unsigned p1 = __shfl_up_sync(FULL, e1, d);
        unsigned p2 = __shfl_up_sync(FULL, e2, d);
        unsigned p3 = __shfl_up_sync(FULL, e3, d);
        if (lane >= d) {
            unsigned n0 = compose4(e0, e1, e2, e3, p0);
            unsigned n1 = compose4(e0, e1, e2, e3, p1);
            unsigned n2 = compose4(e0, e1, e2, e3, p2);
            unsigned n3 = compose4(e0, e1, e2, e3, p3);
            e0 = n0; e1 = n1; e2 = n2; e3 = n3;
        }
    }
    if (lane == 31) {
        wm_s[wid * 4 + 0] = e0; wm_s[wid * 4 + 1] = e1;
        wm_s[wid * 4 + 2] = e2; wm_s[wid * 4 + 3] = e3;
    }
    __syncthreads();

    // ---- inter-warp composition scan of the 16 warp maps (warp 0) ----
    if (wid == 0) {
        unsigned f0 = (lane < 16) ? wm_s[lane * 4 + 0] : 0u;
        unsigned f1 = (lane < 16) ? wm_s[lane * 4 + 1] : 1u;
        unsigned f2 = (lane < 16) ? wm_s[lane * 4 + 2] : 2u;
        unsigned f3 = (lane < 16) ? wm_s[lane * 4 + 3] : 3u;
        #pragma unroll
        for (int d = 1; d < 16; d <<= 1) {
            unsigned p0 = __shfl_up_sync(FULL, f0, d);
            unsigned p1 = __shfl_up_sync(FULL, f1, d);
            unsigned p2 = __shfl_up_sync(FULL, f2, d);
            unsigned p3 = __shfl_up_sync(FULL, f3, d);
            if (lane >= d && lane < 16) {
                unsigned n0 = compose4(f0, f1, f2, f3, p0);
                unsigned n1 = compose4(f0, f1, f2, f3, p1);
                unsigned n2 = compose4(f0, f1, f2, f3, p2);
                unsigned n3 = compose4(f0, f1, f2, f3, p3);
                f0 = n0; f1 = n1; f2 = n2; f3 = n3;
            }
        }
        if (lane < 16)  wb0_s[lane + 1] = f0;
        if (lane == 31) wb0_s[0] = 0u;
    }
    __syncthreads();

    g0_s[t] = compose4(e0, e1, e2, e3, wb0_s[wid]);
    __syncthreads();

    // ================= phase B: walk real path, histogram patch sums =========
    {
        unsigned ge = (t == 0) ? 0u : g0_s[t - 1];
        int m = CH * t + (int)(ge & 3u);
        const int mend = CH * (t + 1);
        int* hw = &hist_s[wid * 64];
        while (m < mend) {
            int pk  = pk_s[m];
            int bit = pk & 1;
            int s   = bit ? 1 : 4;
            if (m < M3) {
                if (m + s <= 2730) {
                    int q;
                    if (bit) q = (pk >> 1) << 2;          // mean = sum3/3 = q/12
                    else q = (pk >> 1) + (pk_s[m+1] >> 1) + (pk_s[m+2] >> 1)
                           + (pk_s[m+3] >> 1);            // mean = q/12
                    atomicAdd(&hw[q], 1);
                } else {
                    // clipped final patch: j = L; padded bytes are zero
                    int fs = (pk >> 1);
                    if (!bit) fs += (pk_s[m+1] >> 1) + (pk_s[m+2] >> 1)
                                  + (pk_s[m+3] >> 1);
                    clip_mean_s = (float)fs / (float)(LL - 3 * m);
                    clip_flag_s = 1;
                }
            }
            m += s;
        }
    }
    __syncthreads();

    if (t < 49) {
        int s = 0;
        #pragma unroll
        for (int w = 0; w < 16; w++) s += hist_s[w * 64 + t];
        hist_tot_s[t] = s;
    }
    __syncthreads();

    // ================= MLP: hist-weighted relu accumulate ====================
    {
        int e = t & 63;
        int g = t >> 6;                  // 0..7
        float w1e = w1[e];
        float b1e = b1[e];
        float acc = 0.0f;
        int q0 = g * 7;
        int q1 = q0 + 7; if (q1 > 49) q1 = 49;
        for (int q = q0; q < q1; q++) {
            int c = hist_tot_s[q];
            if (c) acc += (float)c * fmaxf(fmaf((float)q * (1.0f / 12.0f), w1e, b1e), 0.0f);
        }
        if (g == 0 && clip_flag_s)
            acc += fmaxf(fmaf(clip_mean_s, w1e, b1e), 0.0f);
        hpart_s[g * EE + e] = acc;
    }
    __syncthreads();

    if (t < EE) {
        float npf = (float)(g0_s[NT - 1] >> 2);
        float s = 0.0f;
        #pragma unroll
        for (int g = 0; g < 8; g++) s += hpart_s[g * EE + t];
        havg_s[t] = s / npf;
    }
    __syncthreads();

    // ---- final 64x64 GEMV ----
    if (t < EE) {
        const float4* w2r = reinterpret_cast<const float4*>(w2 + t * EE);
        float f = b2[t];
        #pragma unroll
        for (int kk = 0; kk < 16; kk++) {
            float4 wv = w2r[kk];
            f = fmaf(havg_s[4 * kk + 0], wv.x, f);
            f = fmaf(havg_s[4 * kk + 1], wv.y, f);
            f = fmaf(havg_s[4 * kk + 2], wv.z, f);
            f = fmaf(havg_s[4 * kk + 3], wv.w, f);
        }
        out_feat[(long)b * EE + t] = f;
    }
}

extern "C" void kernel_launch(void* const* d_in, const int* in_sizes, int n_in,
                              void* d_out, int out_size) {
    const int*   x  = (const int*)d_in[0];
    const float* w1 = (const float*)d_in[1];
    const float* b1 = (const float*)d_in[2];
    const float* w2 = (const float*)d_in[3];
    const float* b2 = (const float*)d_in[4];
    float* out = (float*)d_out;
    patcher_kernel<<<BB, NT>>>(x, w1, b1, w2, b2, out, out + BB * EE);
}